// round 14
// baseline (speedup 1.0000x reference)
#include <cuda_runtime.h>
#include <cuda_bf16.h>
#include <math.h>
#include <stdint.h>

#define B_  2
#define S_  2048
#define D_  1024
#define H_  16
#define DH_ 64
#define MTOT (B_*S_)   // 4096
#define MD_ ((size_t)MTOT*D_)
#define DD_ ((size_t)D_*D_)

__device__ float g_V[MTOT*D_];
__device__ __nv_bfloat16 g_Xhi3[3*MTOT*D_];
__device__ __nv_bfloat16 g_Xlo3[3*MTOT*D_];
__device__ __nv_bfloat16 g_Whi4[4*D_*D_];
__device__ __nv_bfloat16 g_Wlo4[4*D_*D_];
__device__ __nv_bfloat16 g_Qhi[MTOT*D_];
__device__ __nv_bfloat16 g_Qlo[MTOT*D_];
__device__ __nv_bfloat16 g_Khi[MTOT*D_];
__device__ __nv_bfloat16 g_Klo[MTOT*D_];
__device__ __nv_bfloat16 g_Vthi[MTOT*D_];   // [bh][d][s]
__device__ __nv_bfloat16 g_Vtlo[MTOT*D_];
__device__ __nv_bfloat16 g_Chi[MTOT*D_];
__device__ __nv_bfloat16 g_Clo[MTOT*D_];

#define SW128(o) ((o) ^ (((o) >> 3) & 0x70))

static __device__ __forceinline__ uint32_t s2u(const void* p) {
    uint32_t a;
    asm("{ .reg .u64 t; cvta.to.shared.u64 t, %1; cvt.u32.u64 %0, t; }" : "=r"(a) : "l"(p));
    return a;
}
static __device__ __forceinline__ void ldm4(uint32_t* r, uint32_t addr) {
    asm volatile("ldmatrix.sync.aligned.m8n8.x4.shared.b16 {%0,%1,%2,%3}, [%4];"
        : "=r"(r[0]), "=r"(r[1]), "=r"(r[2]), "=r"(r[3]) : "r"(addr));
}
static __device__ __forceinline__ void mma_bf16(float* c, const uint32_t* a, const uint32_t* b) {
    asm volatile("mma.sync.aligned.m16n8k16.row.col.f32.bf16.bf16.f32 "
        "{%0,%1,%2,%3}, {%4,%5,%6,%7}, {%8,%9}, {%0,%1,%2,%3};"
        : "+f"(c[0]), "+f"(c[1]), "+f"(c[2]), "+f"(c[3])
        : "r"(a[0]), "r"(a[1]), "r"(a[2]), "r"(a[3]), "r"(b[0]), "r"(b[1]));
}
static __device__ __forceinline__ void splitfast(float x, float y, uint32_t& hi, uint32_t& lo) {
    asm("cvt.rn.bf16x2.f32 %0, %1, %2;" : "=r"(hi) : "f"(y), "f"(x));
    float hx = __uint_as_float(hi << 16);
    float hy = __uint_as_float(hi & 0xFFFF0000u);
    float lx = x - hx, ly = y - hy;
    asm("cvt.rn.bf16x2.f32 %0, %1, %2;" : "=r"(lo) : "f"(ly), "f"(lx));
}
static __device__ __forceinline__ void cp16(uint32_t sa, const void* ga) {
    asm volatile("cp.async.cg.shared.global [%0], [%1], 16;" :: "r"(sa), "l"(ga));
}
#define CP_COMMIT() asm volatile("cp.async.commit_group;" ::: "memory")
#define CP_WAIT0()  asm volatile("cp.async.wait_group 0;" ::: "memory")
#define CP_WAIT1()  asm volatile("cp.async.wait_group 1;" ::: "memory")

// ===========================================================================
// Batched fp32 -> bf16 hi/lo splits
// ===========================================================================
__global__ __launch_bounds__(256) void splitx_kernel(
    const float* __restrict__ q, const float* __restrict__ k,
    const float* __restrict__ v)
{
    const int z = blockIdx.z;
    const float* x = (z == 0) ? q : (z == 1) ? k : v;
    size_t off = (size_t)z * MD_;
    int i = blockIdx.x * 256 + threadIdx.x;
    float4 v0 = ((const float4*)x)[2*i];
    float4 v1 = ((const float4*)x)[2*i+1];
    uint4 hv, lv;
    splitfast(v0.x, v0.y, hv.x, lv.x);
    splitfast(v0.z, v0.w, hv.y, lv.y);
    splitfast(v1.x, v1.y, hv.z, lv.z);
    splitfast(v1.z, v1.w, hv.w, lv.w);
    ((uint4*)(g_Xhi3 + off))[i] = hv;
    ((uint4*)(g_Xlo3 + off))[i] = lv;
}

__global__ __launch_bounds__(256) void splitw_kernel(
    const float* __restrict__ wq, const float* __restrict__ wk,
    const float* __restrict__ wv, const float* __restrict__ wo)
{
    const int z = blockIdx.z;
    const float* x = (z == 0) ? wq : (z == 1) ? wk : (z == 2) ? wv : wo;
    size_t off = (size_t)z * DD_;
    int i = blockIdx.x * 256 + threadIdx.x;
    float4 v0 = ((const float4*)x)[2*i];
    float4 v1 = ((const float4*)x)[2*i+1];
    uint4 hv, lv;
    splitfast(v0.x, v0.y, hv.x, lv.x);
    splitfast(v0.z, v0.w, hv.y, lv.y);
    splitfast(v1.x, v1.y, hv.z, lv.z);
    splitfast(v1.z, v1.w, hv.w, lv.w);
    ((uint4*)(g_Whi4 + off))[i] = hv;
    ((uint4*)(g_Wlo4 + off))[i] = lv;
}

// ===========================================================================
// GEMM mainloop: 128x128 tile, BK=64, 3-stage cp.async.
// ===========================================================================
__device__ __forceinline__ void load_chunk_async(
    uint32_t sbase, int kc,
    const __nv_bfloat16* Ahi, const __nv_bfloat16* Alo,
    const __nv_bfloat16* Bhi, const __nv_bfloat16* Blo,
    int m0, int n0, int tid)
{
    #pragma unroll
    for (int i = 0; i < 4; i++) {
        int idx = tid + i * 256;
        int row = idx >> 3, c8 = idx & 7;
        uint32_t so = SW128((uint32_t)(row * 128 + c8 * 16));
        size_t ga = (size_t)(m0 + row) * D_ + kc * 64 + c8 * 8;
        size_t gb = (size_t)(n0 + row) * D_ + kc * 64 + c8 * 8;
        cp16(sbase + so,          Ahi + ga);
        cp16(sbase + 16384u + so, Alo + ga);
        cp16(sbase + 32768u + so, Bhi + gb);
        cp16(sbase + 49152u + so, Blo + gb);
    }
}

__device__ __forceinline__ void gemm_mainloop(
    uint32_t sb, const __nv_bfloat16* Ahi, const __nv_bfloat16* Alo,
    const __nv_bfloat16* Bhi, const __nv_bfloat16* Blo,
    int m0, int n0, int tid, int lane, int wm, int wn,
    float acc[2][8][4])
{
    const uint32_t swx = (uint32_t)((lane & 7) << 4);
    const int aRowBase = wm * 32 + (lane & 15);
    const uint32_t aKl = (uint32_t)((lane >> 4) << 4);
    const int bRowBase = wn * 64 + ((lane >> 4) << 3) + (lane & 7);
    const uint32_t bKl = (uint32_t)(((lane >> 3) & 1) << 4);

    load_chunk_async(sb,          0, Ahi, Alo, Bhi, Blo, m0, n0, tid); CP_COMMIT();
    load_chunk_async(sb + 65536u, 1, Ahi, Alo, Bhi, Blo, m0, n0, tid); CP_COMMIT();

    int st = 0;
    #pragma unroll 1
    for (int kc = 0; kc < 16; kc++) {
        CP_WAIT1();
        __syncthreads();
        if (kc + 2 < 16) {
            int ps = st + 2; if (ps >= 3) ps -= 3;
            load_chunk_async(sb + (uint32_t)ps * 65536u, kc + 2,
                             Ahi, Alo, Bhi, Blo, m0, n0, tid);
        }
        CP_COMMIT();

        const uint32_t bofs = sb + (uint32_t)st * 65536u;
        #pragma unroll
        for (int kk = 0; kk < 4; kk++) {
            const uint32_t kb = (uint32_t)(kk << 5);
            uint32_t ah[2][4], al[2][4];
            #pragma unroll
            for (int mt = 0; mt < 2; mt++) {
                uint32_t rowoff = (uint32_t)(aRowBase + mt * 16) * 128u;
                uint32_t cofs = (kb + aKl) ^ swx;
                ldm4(ah[mt], bofs + rowoff + cofs);
                ldm4(al[mt], bofs + 16384u + rowoff + cofs);
            }
            #pragma unroll
            for (int ng = 0; ng < 4; ng++) {
                uint32_t rowoff = (uint32_t)(bRowBase + ng * 16) * 128u;
                uint32_t cofs = (kb + bKl) ^ swx;
                uint32_t bh[4], bl[4];
                ldm4(bh, bofs + 32768u + rowoff + cofs);
                ldm4(bl, bofs + 49152u + rowoff + cofs);
                #pragma unroll
                for (int mt = 0; mt < 2; mt++) {
                    mma_bf16(acc[mt][2*ng],   ah[mt], &bh[0]);
                    mma_bf16(acc[mt][2*ng+1], ah[mt], &bh[2]);
                    mma_bf16(acc[mt][2*ng],   ah[mt], &bl[0]);
                    mma_bf16(acc[mt][2*ng+1], ah[mt], &bl[2]);
                    mma_bf16(acc[mt][2*ng],   al[mt], &bh[0]);
                    mma_bf16(acc[mt][2*ng+1], al[mt], &bh[2]);
                }
            }
        }
        if (++st == 3) st = 0;
    }
}

// ===========================================================================
// Fused QKV projection: grid.z selects (X, W, bias, epilogue).
// z=0 (Q), z=1 (K): rope + split epilogue. z=2 (V): fp32 store.
// ===========================================================================
__global__ __launch_bounds__(256, 1) void gemm_qkv_kernel(
    const float* __restrict__ bq, const float* __restrict__ bk,
    const float* __restrict__ bv)
{
    extern __shared__ char smem[];
    __shared__ float sinv[32];
    const int tid = threadIdx.x, lane = tid & 31, wid = tid >> 5;
    const int wm = wid & 3, wn = wid >> 2;
    const int z = blockIdx.z;
    const int m0 = blockIdx.y * 128, n0 = blockIdx.x * 128;
    const uint32_t sb = s2u(smem);

    if (tid < 32) {
        float coef = -(4.0f * logf(10.0f)) / 64.0f;
        float arg  = (float)(2 * tid) * coef;
        sinv[tid] = (float)exp((double)arg);
    }

    const __nv_bfloat16* Ahi = g_Xhi3 + (size_t)z * MD_;
    const __nv_bfloat16* Alo = g_Xlo3 + (size_t)z * MD_;
    const __nv_bfloat16* Bhi = g_Whi4 + (size_t)z * DD_;
    const __nv_bfloat16* Blo = g_Wlo4 + (size_t)z * DD_;
    const float* bias = (z == 0) ? bq : (z == 1) ? bk : bv;

    float acc[2][8][4];
    #pragma unroll
    for (int mt = 0; mt < 2; mt++)
        #pragma unroll
        for (int nt = 0; nt < 8; nt++)
            #pragma unroll
            for (int r = 0; r < 4; r++) acc[mt][nt][r] = 0.f;

    gemm_mainloop(sb, Ahi, Alo, Bhi, Blo, m0, n0, tid, lane, wm, wn, acc);

    if (z == 2) {
        #pragma unroll
        for (int mt = 0; mt < 2; mt++) {
            int r0 = m0 + wm * 32 + mt * 16 + (lane >> 2);
            #pragma unroll
            for (int nt = 0; nt < 8; nt++) {
                int c = n0 + wn * 64 + nt * 8 + ((lane & 3) << 1);
                float2 bb = *(const float2*)&bias[c];
                *(float2*)&g_V[(size_t)r0 * D_ + c] =
                    make_float2(acc[mt][nt][0] + bb.x, acc[mt][nt][1] + bb.y);
                *(float2*)&g_V[(size_t)(r0 + 8) * D_ + c] =
                    make_float2(acc[mt][nt][2] + bb.x, acc[mt][nt][3] + bb.y);
            }
        }
    } else {
        __nv_bfloat16* dhi = z ? g_Khi : g_Qhi;
        __nv_bfloat16* dlo = z ? g_Klo : g_Qlo;
        #pragma unroll
        for (int mt = 0; mt < 2; mt++) {
            int r0 = m0 + wm * 32 + mt * 16 + (lane >> 2);
            #pragma unroll
            for (int nt = 0; nt < 8; nt++) {
                int c = n0 + wn * 64 + nt * 8 + ((lane & 3) << 1);
                float2 bb = *(const float2*)&bias[c];
                float inv = sinv[(c & 63) >> 1];
                uint32_t hi, lo;
                {
                    int s = r0 & (S_ - 1);
                    float sn, cs;
                    sincosf((float)s * inv, &sn, &cs);
                    float x1 = acc[mt][nt][0] + bb.x;
                    float x2 = acc[mt][nt][1] + bb.y;
                    splitfast(x1 * sn - x2 * cs, -x1 * cs - x2 * sn, hi, lo);
                    *(uint32_t*)&dhi[(size_t)r0 * D_ + c] = hi;
                    *(uint32_t*)&dlo[(size_t)r0 * D_ + c] = lo;
                }
                {
                    int s = (r0 + 8) & (S_ - 1);
                    float sn, cs;
                    sincosf((float)s * inv, &sn, &cs);
                    float x1 = acc[mt][nt][2] + bb.x;
                    float x2 = acc[mt][nt][3] + bb.y;
                    splitfast(x1 * sn - x2 * cs, -x1 * cs - x2 * sn, hi, lo);
                    *(uint32_t*)&dhi[(size_t)(r0 + 8) * D_ + c] = hi;
                    *(uint32_t*)&dlo[(size_t)(r0 + 8) * D_ + c] = lo;
                }
            }
        }
    }
}

// ===========================================================================
// Output projection: C (split) @ Wo^T + bo -> fp32 out
// ===========================================================================
__global__ __launch_bounds__(256, 1) void gemm_o_kernel(
    const float* __restrict__ bias, float* __restrict__ Y)
{
    extern __shared__ char smem[];
    const int tid = threadIdx.x, lane = tid & 31, wid = tid >> 5;
    const int wm = wid & 3, wn = wid >> 2;
    const int m0 = blockIdx.y * 128, n0 = blockIdx.x * 128;
    const uint32_t sb = s2u(smem);

    float acc[2][8][4];
    #pragma unroll
    for (int mt = 0; mt < 2; mt++)
        #pragma unroll
        for (int nt = 0; nt < 8; nt++)
            #pragma unroll
            for (int r = 0; r < 4; r++) acc[mt][nt][r] = 0.f;

    gemm_mainloop(sb, g_Chi, g_Clo, g_Whi4 + 3 * DD_, g_Wlo4 + 3 * DD_,
                  m0, n0, tid, lane, wm, wn, acc);

    #pragma unroll
    for (int mt = 0; mt < 2; mt++) {
        int r0 = m0 + wm * 32 + mt * 16 + (lane >> 2);
        #pragma unroll
        for (int nt = 0; nt < 8; nt++) {
            int c = n0 + wn * 64 + nt * 8 + ((lane & 3) << 1);
            float2 bb = *(const float2*)&bias[c];
            *(float2*)&Y[(size_t)r0 * D_ + c] =
                make_float2(acc[mt][nt][0] + bb.x, acc[mt][nt][1] + bb.y);
            *(float2*)&Y[(size_t)(r0 + 8) * D_ + c] =
                make_float2(acc[mt][nt][2] + bb.x, acc[mt][nt][3] + bb.y);
        }
    }
}

// ===========================================================================
// V transpose + split: g_V [b,s,h,d] -> g_Vt{hi,lo} [bh, d, s]
// ===========================================================================
__global__ __launch_bounds__(256) void vtrans_kernel()
{
    __shared__ float sst[64][65];
    const int tid = threadIdx.x;
    const int st = blockIdx.x, bh = blockIdx.y;
    const int b = bh >> 4, h = bh & 15;

    #pragma unroll
    for (int it = 0; it < 4; it++) {
        int r = it * 16 + (tid >> 4);
        int c = (tid & 15) << 2;
        float4 v = *(const float4*)&g_V[(size_t)(b*S_ + st*64 + r)*D_ + h*DH_ + c];
        sst[r][c+0] = v.x; sst[r][c+1] = v.y; sst[r][c+2] = v.z; sst[r][c+3] = v.w;
    }
    __syncthreads();

    const int d = tid >> 2;
    const int cb = (tid & 3) << 4;
    uint32_t hi[8], lo[8];
    #pragma unroll
    for (int i = 0; i < 8; i++)
        splitfast(sst[cb + 2*i][d], sst[cb + 2*i + 1][d], hi[i], lo[i]);
    size_t ga = (size_t)(bh * 64 + d) * S_ + st * 64 + cb;
    *(uint4*)&g_Vthi[ga]     = make_uint4(hi[0], hi[1], hi[2], hi[3]);
    *(uint4*)&g_Vthi[ga + 8] = make_uint4(hi[4], hi[5], hi[6], hi[7]);
    *(uint4*)&g_Vtlo[ga]     = make_uint4(lo[0], lo[1], lo[2], lo[3]);
    *(uint4*)&g_Vtlo[ga + 8] = make_uint4(lo[4], lo[5], lo[6], lo[7]);
}

// ===========================================================================
// Causal flash attention, warp-pair column split:
//   512 threads = 16 warps. Warp w: rows (w&7)*16..+15, kv-cols (w>>3)*32..+31.
//   Per-warp state halves (sc[4][4], 16 exps) -> ~110 regs, no spills,
//   4 warps/SMSP. Cross-half row-max via smem (1 barrier/tile); l and O
//   kept as per-half partials, combined once in the epilogue.
// smem: Q 32K | 2 KV stages 64K | max-exch 1K | l-exch 0.5K
// ===========================================================================
__device__ __forceinline__ void load_kv_async512(uint32_t sstage, int kb,
                                                 int b, int bh, int h, int tid)
{
    int row = tid >> 3, c8 = tid & 7;   // 512 threads = 64 rows x 8 chunks
    uint32_t so = SW128((uint32_t)(row * 128 + c8 * 16));
    size_t gk = (size_t)(b*S_ + kb*64 + row) * D_ + h*DH_ + c8*8;
    size_t gv = (size_t)(bh*64 + row) * S_ + (size_t)kb*64 + c8*8;
    cp16(sstage + so,          g_Khi + gk);
    cp16(sstage + 8192u  + so, g_Klo + gk);
    cp16(sstage + 16384u + so, g_Vthi + gv);
    cp16(sstage + 24576u + so, g_Vtlo + gv);
}

__global__ __launch_bounds__(512, 1) void attn_mma_kernel()
{
    extern __shared__ char smA[];
    const uint32_t QHI = 0, QLO = 16384, STG0 = 32768;
    const uint32_t EXM = 98304;           // 2 x 128 floats (max exchange)
    const uint32_t EXL = 98304 + 1024;    // 128 floats (l exchange)
    const uint32_t sb = s2u(smA);
    const int tid = threadIdx.x, lane = tid & 31, w = tid >> 5;
    const int rg = w & 7, ch = w >> 3;
    const int qb = gridDim.x - 1 - blockIdx.x;
    const int bh = blockIdx.y, b = bh >> 4, h = bh & 15;

    // Load Q tile (hi+lo): 512 threads, 2 iters per array
    #pragma unroll
    for (int i = 0; i < 2; i++) {
        int idx = tid + i * 512, row = idx >> 3, c8 = idx & 7;
        uint32_t so = SW128((uint32_t)(row * 128 + c8 * 16));
        size_t ga = (size_t)(b*S_ + qb*128 + row) * D_ + h*DH_ + c8*8;
        *(uint4*)(smA + QHI + so) = *(const uint4*)(g_Qhi + ga);
        *(uint4*)(smA + QLO + so) = *(const uint4*)(g_Qlo + ga);
    }
    load_kv_async512(sb + STG0, 0, b, bh, h, tid);
    CP_COMMIT();
    __syncthreads();

    const uint32_t swx  = (uint32_t)((lane & 7) << 4);
    const uint32_t aRow = (uint32_t)(rg * 16 + (lane & 15));
    const uint32_t aKl  = (uint32_t)((lane >> 4) << 4);
    const uint32_t bRow = (uint32_t)(((lane >> 4) << 3) + (lane & 7));
    const uint32_t bKl  = (uint32_t)(((lane >> 3) & 1) << 4);

    // Persistent Q fragments (full d range)
    uint32_t qh[4][4], ql[4][4];
    #pragma unroll
    for (int kk = 0; kk < 4; kk++) {
        uint32_t cofs = ((uint32_t)(kk << 5) + aKl) ^ swx;
        ldm4(qh[kk], sb + QHI + aRow * 128u + cofs);
        ldm4(ql[kk], sb + QLO + aRow * 128u + cofs);
    }

    float m_a = -1e30f, m_b = -1e30f, l_a = 0.f, l_b = 0.f;  // l = per-half partial
    float oc[8][4];                                           // per-half partial O
    #pragma unroll
    for (int t = 0; t < 8; t++)
        #pragma unroll
        for (int r = 0; r < 4; r++) oc[t][r] = 0.f;

    float* exm = (float*)(smA + EXM);
    const int rowA = rg * 16 + (lane >> 2);      // 'a' row within tile
    const int rga  = qb * 128 + rowA;            // global q row (a); b row = +8

    const int nkb = 2 * qb + 2;
    #pragma unroll 1
    for (int kb = 0; kb < nkb; kb++) {
        CP_WAIT0();
        __syncthreads();
        const uint32_t sst = sb + STG0 + (uint32_t)(kb & 1) * 32768u;
        if (kb + 1 < nkb)
            load_kv_async512(sb + STG0 + (uint32_t)((kb + 1) & 1) * 32768u,
                             kb + 1, b, bh, h, tid);
        CP_COMMIT();

        // S = Q K^T over this warp's 32 kv columns (3-term split)
        float sc[4][4];
        #pragma unroll
        for (int t = 0; t < 4; t++)
            #pragma unroll
            for (int r = 0; r < 4; r++) sc[t][r] = 0.f;
        #pragma unroll
        for (int kk = 0; kk < 4; kk++) {
            uint32_t cofs = ((uint32_t)(kk << 5) + bKl) ^ swx;
            #pragma unroll
            for (int g = 0; g < 2; g++) {
                uint32_t ro = (uint32_t)(ch * 32 + g * 16 + bRow) * 128u;
                uint32_t kh[4], kl[4];
                ldm4(kh, sst + ro + cofs);
                ldm4(kl, sst + 8192u + ro + cofs);
                mma_bf16(sc[2*g],   qh[kk], &kh[0]);
                mma_bf16(sc[2*g+1], qh[kk], &kh[2]);
                mma_bf16(sc[2*g],   qh[kk], &kl[0]);
                mma_bf16(sc[2*g+1], qh[kk], &kl[2]);
                mma_bf16(sc[2*g],   ql[kk], &kh[0]);
                mma_bf16(sc[2*g+1], ql[kk], &kh[2]);
            }
        }

        // causal mask
        if (kb >= 2*qb) {
            #pragma unroll
            for (int t = 0; t < 4; t++) {
                int cg = kb*64 + ch*32 + t*8 + ((lane & 3) << 1);
                if (cg     > rga)     sc[t][0] = -1e30f;
                if (cg + 1 > rga)     sc[t][1] = -1e30f;
                if (cg     > rga + 8) sc[t][2] = -1e30f;
                if (cg + 1 > rga + 8) sc[t][3] = -1e30f;
            }
        }

        // local (half-row) max, quad reduce
        float mxa = -1e30f, mxb = -1e30f;
        #pragma unroll
        for (int t = 0; t < 4; t++) {
            mxa = fmaxf(mxa, fmaxf(sc[t][0], sc[t][1]));
            mxb = fmaxf(mxb, fmaxf(sc[t][2], sc[t][3]));
        }
        mxa = fmaxf(mxa, __shfl_xor_sync(0xffffffffu, mxa, 1));
        mxa = fmaxf(mxa, __shfl_xor_sync(0xffffffffu, mxa, 2));
        mxb = fmaxf(mxb, __shfl_xor_sync(0xffffffffu, mxb, 1));
        mxb = fmaxf(mxb, __shfl_xor_sync(0xffffffffu, mxb, 2));
        // cross-half max exchange
        if ((lane & 3) == 0) {
            exm[ch*128 + rowA]     = mxa;
            exm[ch*128 + rowA + 8] = mxb;
        }
        __syncthreads();
        mxa = fmaxf(mxa, exm[(ch^1)*128 + rowA]);
        mxb = fmaxf(mxb, exm[(ch^1)*128 + rowA + 8]);

        float mna = fmaxf(m_a, mxa), mnb = fmaxf(m_b, mxb);
        float alpa = __expf(m_a - mna), alpb = __expf(m_b - mnb);
        float psa = 0.f, psb = 0.f;
        #pragma unroll
        for (int t = 0; t < 4; t++) {
            sc[t][0] = __expf(sc[t][0] - mna); psa += sc[t][0];
            sc[t][1] = __expf(sc[t][1] - mna); psa += sc[t][1];
            sc[t][2] = __expf(sc[t][2] - mnb); psb += sc[t][2];
            sc[t][3] = __expf(sc[t][3] - mnb); psb += sc[t][3];
        }
        psa += __shfl_xor_sync(0xffffffffu, psa, 1);
        psa += __shfl_xor_sync(0xffffffffu, psa, 2);
        psb += __shfl_xor_sync(0xffffffffu, psb, 1);
        psb += __shfl_xor_sync(0xffffffffu, psb, 2);
        l_a = l_a * alpa + psa;  m_a = mna;   // per-half partial l
        l_b = l_b * alpb + psb;  m_b = mnb;
        #pragma unroll
        for (int t = 0; t < 8; t++) {
            oc[t][0] *= alpa; oc[t][1] *= alpa;
            oc[t][2] *= alpb; oc[t][3] *= alpb;
        }

        // O_partial += P_half V_half   (k-steps of this column half)
        #pragma unroll
        for (int j = 0; j < 2; j++) {
            int kkg = ch * 2 + j;
            uint32_t ph[4], pl[4];
            splitfast(sc[2*j][0],   sc[2*j][1],   ph[0], pl[0]);
            splitfast(sc[2*j][2],   sc[2*j][3],   ph[1], pl[1]);
            splitfast(sc[2*j+1][0], sc[2*j+1][1], ph[2], pl[2]);
            splitfast(sc[2*j+1][2], sc[2*j+1][3], ph[3], pl[3]);
            uint32_t cofs = ((uint32_t)(kkg << 5) + bKl) ^ swx;
            #pragma unroll
            for (int ng = 0; ng < 4; ng++) {
                uint32_t ro = (bRow + (uint32_t)(ng * 16)) * 128u;
                uint32_t vh[4], vl[4];
                ldm4(vh, sst + 16384u + ro + cofs);
                ldm4(vl, sst + 24576u + ro + cofs);
                mma_bf16(oc[2*ng],   ph, &vh[0]);
                mma_bf16(oc[2*ng+1], ph, &vh[2]);
                mma_bf16(oc[2*ng],   ph, &vl[0]);
                mma_bf16(oc[2*ng+1], ph, &vl[2]);
                mma_bf16(oc[2*ng],   pl, &vh[0]);
                mma_bf16(oc[2*ng+1], pl, &vh[2]);
            }
        }
    }

    // Epilogue: combine partial O and l across column halves, then store.
    __syncthreads();                       // PV reads of stage smem complete
    float* red = (float*)(smA + STG0);     // 32KB reduction buffer
    float* exl = (float*)(smA + EXL);
    if (ch == 1) {
        float* dst = red + (size_t)(rg * 32 + lane) * 32;
        #pragma unroll
        for (int t = 0; t < 8; t++)
            #pragma unroll
            for (int r = 0; r < 4; r++) dst[t*4 + r] = oc[t][r];
        if ((lane & 3) == 0) {
            exl[rowA]     = l_a;
            exl[rowA + 8] = l_b;
        }
    }
    __syncthreads();
    if (ch == 0) {
        const float* src = red + (size_t)(rg * 32 + lane) * 32;
        #pragma unroll
        for (int t = 0; t < 8; t++)
            #pragma unroll
            for (int r = 0; r < 4; r++) oc[t][r] += src[t*4 + r];
        l_a += exl[rowA];
        l_b += exl[rowA + 8];

        float inva = 1.f / l_a, invb = 1.f / l_b;
        size_t baseA = (size_t)(b*S_ + qb*128 + rowA) * D_ + h*DH_;
        size_t baseB = baseA + (size_t)8 * D_;
        #pragma unroll
        for (int t = 0; t < 8; t++) {
            int d = t*8 + ((lane & 3) << 1);
            uint32_t hi, lo;
            splitfast(oc[t][0]*inva, oc[t][1]*inva, hi, lo);
            *(uint32_t*)&g_Chi[baseA + d] = hi;
            *(uint32_t*)&g_Clo[baseA + d] = lo;
            splitfast(oc[t][2]*invb, oc[t][3]*invb, hi, lo);
            *(uint32_t*)&g_Chi[baseB + d] = hi;
            *(uint32_t*)&g_Clo[baseB + d] = lo;
        }
    }
}

// ===========================================================================
extern "C" void kernel_launch(void* const* d_in, const int* in_sizes, int n_in,
                              void* d_out, int out_size)
{
    const float* q  = (const float*)d_in[0];
    const float* k  = (const float*)d_in[1];
    const float* v  = (const float*)d_in[2];
    const float* Wq = (const float*)d_in[3];
    const float* bq = (const float*)d_in[4];
    const float* Wk = (const float*)d_in[5];
    const float* bk = (const float*)d_in[6];
    const float* Wv = (const float*)d_in[7];
    const float* bv = (const float*)d_in[8];
    const float* Wo = (const float*)d_in[9];
    const float* bo = (const float*)d_in[10];
    float* out = (float*)d_out;

    const int gsmem = 3 * 65536;  // 196608
    cudaFuncSetAttribute(gemm_qkv_kernel, cudaFuncAttributeMaxDynamicSharedMemorySize, gsmem);
    cudaFuncSetAttribute(gemm_o_kernel,   cudaFuncAttributeMaxDynamicSharedMemorySize, gsmem);
    const int asmem = 98304 + 1024 + 512;  // 99840
    cudaFuncSetAttribute(attn_mma_kernel, cudaFuncAttributeMaxDynamicSharedMemorySize, asmem);

    const int NXB = (int)(MD_/8)/256;   // 2048
    const int NWB = (int)(DD_/8)/256;   // 512

    splitw_kernel<<<dim3(NWB, 1, 4), 256>>>(Wq, Wk, Wv, Wo);
    splitx_kernel<<<dim3(NXB, 1, 3), 256>>>(q, k, v);

    gemm_qkv_kernel<<<dim3(D_/128, MTOT/128, 3), 256, gsmem>>>(bq, bk, bv);

    vtrans_kernel<<<dim3(S_/64, B_*H_), 256>>>();

    attn_mma_kernel<<<dim3(S_/128, B_*H_), 512, asmem>>>();

    gemm_o_kernel<<<dim3(D_/128, MTOT/128), 256, gsmem>>>(bo, out);
}

// round 15
// speedup vs baseline: 1.0526x; 1.0526x over previous
#include <cuda_runtime.h>
#include <cuda_bf16.h>
#include <math.h>
#include <stdint.h>

#define B_  2
#define S_  2048
#define D_  1024
#define H_  16
#define DH_ 64
#define MTOT (B_*S_)   // 4096
#define MD_ ((size_t)MTOT*D_)
#define DD_ ((size_t)D_*D_)

__device__ float g_V[MTOT*D_];
__device__ __nv_bfloat16 g_Xhi3[3*MTOT*D_];
__device__ __nv_bfloat16 g_Xlo3[3*MTOT*D_];
__device__ __nv_bfloat16 g_Whi4[4*D_*D_];
__device__ __nv_bfloat16 g_Wlo4[4*D_*D_];
__device__ __nv_bfloat16 g_Qhi[MTOT*D_];
__device__ __nv_bfloat16 g_Qlo[MTOT*D_];
__device__ __nv_bfloat16 g_Khi[MTOT*D_];
__device__ __nv_bfloat16 g_Klo[MTOT*D_];
__device__ __nv_bfloat16 g_Vthi[MTOT*D_];   // [bh][d][s]
__device__ __nv_bfloat16 g_Vtlo[MTOT*D_];
__device__ __nv_bfloat16 g_Chi[MTOT*D_];
__device__ __nv_bfloat16 g_Clo[MTOT*D_];

#define SW128(o) ((o) ^ (((o) >> 3) & 0x70))

static __device__ __forceinline__ uint32_t s2u(const void* p) {
    uint32_t a;
    asm("{ .reg .u64 t; cvta.to.shared.u64 t, %1; cvt.u32.u64 %0, t; }" : "=r"(a) : "l"(p));
    return a;
}
static __device__ __forceinline__ void ldm4(uint32_t* r, uint32_t addr) {
    asm volatile("ldmatrix.sync.aligned.m8n8.x4.shared.b16 {%0,%1,%2,%3}, [%4];"
        : "=r"(r[0]), "=r"(r[1]), "=r"(r[2]), "=r"(r[3]) : "r"(addr));
}
static __device__ __forceinline__ void mma_bf16(float* c, const uint32_t* a, const uint32_t* b) {
    asm volatile("mma.sync.aligned.m16n8k16.row.col.f32.bf16.bf16.f32 "
        "{%0,%1,%2,%3}, {%4,%5,%6,%7}, {%8,%9}, {%0,%1,%2,%3};"
        : "+f"(c[0]), "+f"(c[1]), "+f"(c[2]), "+f"(c[3])
        : "r"(a[0]), "r"(a[1]), "r"(a[2]), "r"(a[3]), "r"(b[0]), "r"(b[1]));
}
static __device__ __forceinline__ void splitfast(float x, float y, uint32_t& hi, uint32_t& lo) {
    asm("cvt.rn.bf16x2.f32 %0, %1, %2;" : "=r"(hi) : "f"(y), "f"(x));
    float hx = __uint_as_float(hi << 16);
    float hy = __uint_as_float(hi & 0xFFFF0000u);
    float lx = x - hx, ly = y - hy;
    asm("cvt.rn.bf16x2.f32 %0, %1, %2;" : "=r"(lo) : "f"(ly), "f"(lx));
}
static __device__ __forceinline__ void cp16(uint32_t sa, const void* ga) {
    asm volatile("cp.async.cg.shared.global [%0], [%1], 16;" :: "r"(sa), "l"(ga));
}
#define CP_COMMIT() asm volatile("cp.async.commit_group;" ::: "memory")
#define CP_WAIT1()  asm volatile("cp.async.wait_group 1;" ::: "memory")
#define CP_WAIT1G() asm volatile("cp.async.wait_group 1;" ::: "memory")

// ===========================================================================
// Merged batched fp32 -> bf16 hi/lo splits: z 0..2 = q,k,v ; z 3..6 = weights
// ===========================================================================
__global__ __launch_bounds__(256) void split_all_kernel(
    const float* __restrict__ q, const float* __restrict__ k,
    const float* __restrict__ v,
    const float* __restrict__ wq, const float* __restrict__ wk,
    const float* __restrict__ wv, const float* __restrict__ wo)
{
    const int z = blockIdx.z;
    const float* x;
    __nv_bfloat16 *dhi, *dlo;
    if (z < 3) {
        x = (z == 0) ? q : (z == 1) ? k : v;
        dhi = g_Xhi3 + (size_t)z * MD_;
        dlo = g_Xlo3 + (size_t)z * MD_;
    } else {
        if (blockIdx.x >= 512) return;   // weights need only 512 blocks
        int w = z - 3;
        x = (w == 0) ? wq : (w == 1) ? wk : (w == 2) ? wv : wo;
        dhi = g_Whi4 + (size_t)w * DD_;
        dlo = g_Wlo4 + (size_t)w * DD_;
    }
    int i = blockIdx.x * 256 + threadIdx.x;
    float4 v0 = ((const float4*)x)[2*i];
    float4 v1 = ((const float4*)x)[2*i+1];
    uint4 hv, lv;
    splitfast(v0.x, v0.y, hv.x, lv.x);
    splitfast(v0.z, v0.w, hv.y, lv.y);
    splitfast(v1.x, v1.y, hv.z, lv.z);
    splitfast(v1.z, v1.w, hv.w, lv.w);
    ((uint4*)dhi)[i] = hv;
    ((uint4*)dlo)[i] = lv;
}

// ===========================================================================
// GEMM mainloop: 128x128 tile, BK=64, 3-stage cp.async.
// ===========================================================================
__device__ __forceinline__ void load_chunk_async(
    uint32_t sbase, int kc,
    const __nv_bfloat16* Ahi, const __nv_bfloat16* Alo,
    const __nv_bfloat16* Bhi, const __nv_bfloat16* Blo,
    int m0, int n0, int tid)
{
    #pragma unroll
    for (int i = 0; i < 4; i++) {
        int idx = tid + i * 256;
        int row = idx >> 3, c8 = idx & 7;
        uint32_t so = SW128((uint32_t)(row * 128 + c8 * 16));
        size_t ga = (size_t)(m0 + row) * D_ + kc * 64 + c8 * 8;
        size_t gb = (size_t)(n0 + row) * D_ + kc * 64 + c8 * 8;
        cp16(sbase + so,          Ahi + ga);
        cp16(sbase + 16384u + so, Alo + ga);
        cp16(sbase + 32768u + so, Bhi + gb);
        cp16(sbase + 49152u + so, Blo + gb);
    }
}

__device__ __forceinline__ void gemm_mainloop(
    uint32_t sb, const __nv_bfloat16* Ahi, const __nv_bfloat16* Alo,
    const __nv_bfloat16* Bhi, const __nv_bfloat16* Blo,
    int m0, int n0, int tid, int lane, int wm, int wn,
    float acc[2][8][4])
{
    const uint32_t swx = (uint32_t)((lane & 7) << 4);
    const int aRowBase = wm * 32 + (lane & 15);
    const uint32_t aKl = (uint32_t)((lane >> 4) << 4);
    const int bRowBase = wn * 64 + ((lane >> 4) << 3) + (lane & 7);
    const uint32_t bKl = (uint32_t)(((lane >> 3) & 1) << 4);

    load_chunk_async(sb,          0, Ahi, Alo, Bhi, Blo, m0, n0, tid); CP_COMMIT();
    load_chunk_async(sb + 65536u, 1, Ahi, Alo, Bhi, Blo, m0, n0, tid); CP_COMMIT();

    int st = 0;
    #pragma unroll 1
    for (int kc = 0; kc < 16; kc++) {
        CP_WAIT1();
        __syncthreads();
        if (kc + 2 < 16) {
            int ps = st + 2; if (ps >= 3) ps -= 3;
            load_chunk_async(sb + (uint32_t)ps * 65536u, kc + 2,
                             Ahi, Alo, Bhi, Blo, m0, n0, tid);
        }
        CP_COMMIT();

        const uint32_t bofs = sb + (uint32_t)st * 65536u;
        #pragma unroll
        for (int kk = 0; kk < 4; kk++) {
            const uint32_t kb = (uint32_t)(kk << 5);
            uint32_t ah[2][4], al[2][4];
            #pragma unroll
            for (int mt = 0; mt < 2; mt++) {
                uint32_t rowoff = (uint32_t)(aRowBase + mt * 16) * 128u;
                uint32_t cofs = (kb + aKl) ^ swx;
                ldm4(ah[mt], bofs + rowoff + cofs);
                ldm4(al[mt], bofs + 16384u + rowoff + cofs);
            }
            #pragma unroll
            for (int ng = 0; ng < 4; ng++) {
                uint32_t rowoff = (uint32_t)(bRowBase + ng * 16) * 128u;
                uint32_t cofs = (kb + bKl) ^ swx;
                uint32_t bh[4], bl[4];
                ldm4(bh, bofs + 32768u + rowoff + cofs);
                ldm4(bl, bofs + 49152u + rowoff + cofs);
                #pragma unroll
                for (int mt = 0; mt < 2; mt++) {
                    mma_bf16(acc[mt][2*ng],   ah[mt], &bh[0]);
                    mma_bf16(acc[mt][2*ng+1], ah[mt], &bh[2]);
                    mma_bf16(acc[mt][2*ng],   ah[mt], &bl[0]);
                    mma_bf16(acc[mt][2*ng+1], ah[mt], &bl[2]);
                    mma_bf16(acc[mt][2*ng],   al[mt], &bh[0]);
                    mma_bf16(acc[mt][2*ng+1], al[mt], &bh[2]);
                }
            }
        }
        if (++st == 3) st = 0;
    }
}

// ===========================================================================
// Fused QKV projection: grid.z selects (X, W, bias, epilogue).
// z=0 (Q), z=1 (K): rope + split epilogue. z=2 (V): fp32 store.
// ===========================================================================
__global__ __launch_bounds__(256, 1) void gemm_qkv_kernel(
    const float* __restrict__ bq, const float* __restrict__ bk,
    const float* __restrict__ bv)
{
    extern __shared__ char smem[];
    __shared__ float sinv[32];
    const int tid = threadIdx.x, lane = tid & 31, wid = tid >> 5;
    const int wm = wid & 3, wn = wid >> 2;
    const int z = blockIdx.z;
    const int m0 = blockIdx.y * 128, n0 = blockIdx.x * 128;
    const uint32_t sb = s2u(smem);

    if (tid < 32) {
        float coef = -(4.0f * logf(10.0f)) / 64.0f;
        float arg  = (float)(2 * tid) * coef;
        sinv[tid] = (float)exp((double)arg);
    }

    const __nv_bfloat16* Ahi = g_Xhi3 + (size_t)z * MD_;
    const __nv_bfloat16* Alo = g_Xlo3 + (size_t)z * MD_;
    const __nv_bfloat16* Bhi = g_Whi4 + (size_t)z * DD_;
    const __nv_bfloat16* Blo = g_Wlo4 + (size_t)z * DD_;
    const float* bias = (z == 0) ? bq : (z == 1) ? bk : bv;

    float acc[2][8][4];
    #pragma unroll
    for (int mt = 0; mt < 2; mt++)
        #pragma unroll
        for (int nt = 0; nt < 8; nt++)
            #pragma unroll
            for (int r = 0; r < 4; r++) acc[mt][nt][r] = 0.f;

    gemm_mainloop(sb, Ahi, Alo, Bhi, Blo, m0, n0, tid, lane, wm, wn, acc);

    if (z == 2) {
        #pragma unroll
        for (int mt = 0; mt < 2; mt++) {
            int r0 = m0 + wm * 32 + mt * 16 + (lane >> 2);
            #pragma unroll
            for (int nt = 0; nt < 8; nt++) {
                int c = n0 + wn * 64 + nt * 8 + ((lane & 3) << 1);
                float2 bb = *(const float2*)&bias[c];
                *(float2*)&g_V[(size_t)r0 * D_ + c] =
                    make_float2(acc[mt][nt][0] + bb.x, acc[mt][nt][1] + bb.y);
                *(float2*)&g_V[(size_t)(r0 + 8) * D_ + c] =
                    make_float2(acc[mt][nt][2] + bb.x, acc[mt][nt][3] + bb.y);
            }
        }
    } else {
        __nv_bfloat16* dhi = z ? g_Khi : g_Qhi;
        __nv_bfloat16* dlo = z ? g_Klo : g_Qlo;
        #pragma unroll
        for (int mt = 0; mt < 2; mt++) {
            int r0 = m0 + wm * 32 + mt * 16 + (lane >> 2);
            #pragma unroll
            for (int nt = 0; nt < 8; nt++) {
                int c = n0 + wn * 64 + nt * 8 + ((lane & 3) << 1);
                float2 bb = *(const float2*)&bias[c];
                float inv = sinv[(c & 63) >> 1];
                uint32_t hi, lo;
                {
                    int s = r0 & (S_ - 1);
                    float sn, cs;
                    sincosf((float)s * inv, &sn, &cs);
                    float x1 = acc[mt][nt][0] + bb.x;
                    float x2 = acc[mt][nt][1] + bb.y;
                    splitfast(x1 * sn - x2 * cs, -x1 * cs - x2 * sn, hi, lo);
                    *(uint32_t*)&dhi[(size_t)r0 * D_ + c] = hi;
                    *(uint32_t*)&dlo[(size_t)r0 * D_ + c] = lo;
                }
                {
                    int s = (r0 + 8) & (S_ - 1);
                    float sn, cs;
                    sincosf((float)s * inv, &sn, &cs);
                    float x1 = acc[mt][nt][2] + bb.x;
                    float x2 = acc[mt][nt][3] + bb.y;
                    splitfast(x1 * sn - x2 * cs, -x1 * cs - x2 * sn, hi, lo);
                    *(uint32_t*)&dhi[(size_t)(r0 + 8) * D_ + c] = hi;
                    *(uint32_t*)&dlo[(size_t)(r0 + 8) * D_ + c] = lo;
                }
            }
        }
    }
}

// ===========================================================================
// Output projection: C (split) @ Wo^T + bo -> fp32 out
// ===========================================================================
__global__ __launch_bounds__(256, 1) void gemm_o_kernel(
    const float* __restrict__ bias, float* __restrict__ Y)
{
    extern __shared__ char smem[];
    const int tid = threadIdx.x, lane = tid & 31, wid = tid >> 5;
    const int wm = wid & 3, wn = wid >> 2;
    const int m0 = blockIdx.y * 128, n0 = blockIdx.x * 128;
    const uint32_t sb = s2u(smem);

    float acc[2][8][4];
    #pragma unroll
    for (int mt = 0; mt < 2; mt++)
        #pragma unroll
        for (int nt = 0; nt < 8; nt++)
            #pragma unroll
            for (int r = 0; r < 4; r++) acc[mt][nt][r] = 0.f;

    gemm_mainloop(sb, g_Chi, g_Clo, g_Whi4 + 3 * DD_, g_Wlo4 + 3 * DD_,
                  m0, n0, tid, lane, wm, wn, acc);

    #pragma unroll
    for (int mt = 0; mt < 2; mt++) {
        int r0 = m0 + wm * 32 + mt * 16 + (lane >> 2);
        #pragma unroll
        for (int nt = 0; nt < 8; nt++) {
            int c = n0 + wn * 64 + nt * 8 + ((lane & 3) << 1);
            float2 bb = *(const float2*)&bias[c];
            *(float2*)&Y[(size_t)r0 * D_ + c] =
                make_float2(acc[mt][nt][0] + bb.x, acc[mt][nt][1] + bb.y);
            *(float2*)&Y[(size_t)(r0 + 8) * D_ + c] =
                make_float2(acc[mt][nt][2] + bb.x, acc[mt][nt][3] + bb.y);
        }
    }
}

// ===========================================================================
// V transpose + split: g_V [b,s,h,d] -> g_Vt{hi,lo} [bh, d, s]
// ===========================================================================
__global__ __launch_bounds__(256) void vtrans_kernel()
{
    __shared__ float sst[64][65];
    const int tid = threadIdx.x;
    const int st = blockIdx.x, bh = blockIdx.y;
    const int b = bh >> 4, h = bh & 15;

    #pragma unroll
    for (int it = 0; it < 4; it++) {
        int r = it * 16 + (tid >> 4);
        int c = (tid & 15) << 2;
        float4 v = *(const float4*)&g_V[(size_t)(b*S_ + st*64 + r)*D_ + h*DH_ + c];
        sst[r][c+0] = v.x; sst[r][c+1] = v.y; sst[r][c+2] = v.z; sst[r][c+3] = v.w;
    }
    __syncthreads();

    const int d = tid >> 2;
    const int cb = (tid & 3) << 4;
    uint32_t hi[8], lo[8];
    #pragma unroll
    for (int i = 0; i < 8; i++)
        splitfast(sst[cb + 2*i][d], sst[cb + 2*i + 1][d], hi[i], lo[i]);
    size_t ga = (size_t)(bh * 64 + d) * S_ + st * 64 + cb;
    *(uint4*)&g_Vthi[ga]     = make_uint4(hi[0], hi[1], hi[2], hi[3]);
    *(uint4*)&g_Vthi[ga + 8] = make_uint4(hi[4], hi[5], hi[6], hi[7]);
    *(uint4*)&g_Vtlo[ga]     = make_uint4(lo[0], lo[1], lo[2], lo[3]);
    *(uint4*)&g_Vtlo[ga + 8] = make_uint4(lo[4], lo[5], lo[6], lo[7]);
}

// ===========================================================================
// Causal flash attention (round-12 structure; 3-stage KV ring, 2-deep
// prefetch via wait_group 1). Q tile 128, 256 threads, persistent Q frags.
// smem: Q 32K | 3 KV stages 96K = 128K. 1 CTA/SM.
// ===========================================================================
__device__ __forceinline__ void load_kv_async(uint32_t sstage, int kb,
                                              int b, int bh, int h, int tid)
{
    #pragma unroll
    for (int i = 0; i < 2; i++) {
        int idx = tid + i * 256, row = idx >> 3, c8 = idx & 7;
        uint32_t so = SW128((uint32_t)(row * 128 + c8 * 16));
        size_t gk = (size_t)(b*S_ + kb*64 + row) * D_ + h*DH_ + c8*8;
        size_t gv = (size_t)(bh*64 + row) * S_ + (size_t)kb*64 + c8*8;
        cp16(sstage + so,          g_Khi + gk);
        cp16(sstage + 8192u  + so, g_Klo + gk);
        cp16(sstage + 16384u + so, g_Vthi + gv);
        cp16(sstage + 24576u + so, g_Vtlo + gv);
    }
}

__global__ __launch_bounds__(256, 1) void attn_mma_kernel()
{
    extern __shared__ char smA[];
    const uint32_t QHI = 0, QLO = 16384, STG0 = 32768;
    const uint32_t sb = s2u(smA);
    const int tid = threadIdx.x, lane = tid & 31, wid = tid >> 5;
    const int qb = gridDim.x - 1 - blockIdx.x;
    const int bh = blockIdx.y, b = bh >> 4, h = bh & 15;

    #pragma unroll
    for (int i = 0; i < 4; i++) {
        int idx = tid + i * 256, row = idx >> 3, c8 = idx & 7;
        uint32_t so = SW128((uint32_t)(row * 128 + c8 * 16));
        size_t ga = (size_t)(b*S_ + qb*128 + row) * D_ + h*DH_ + c8*8;
        *(uint4*)(smA + QHI + so) = *(const uint4*)(g_Qhi + ga);
        *(uint4*)(smA + QLO + so) = *(const uint4*)(g_Qlo + ga);
    }

    const int nkb = 2 * qb + 2;
    // prologue: stage0 <- t0, stage1 <- t1 (2 groups outstanding)
    load_kv_async(sb + STG0, 0, b, bh, h, tid);
    CP_COMMIT();
    if (nkb > 1) load_kv_async(sb + STG0 + 32768u, 1, b, bh, h, tid);
    CP_COMMIT();

    const uint32_t swx  = (uint32_t)((lane & 7) << 4);
    const uint32_t aRow = (uint32_t)(wid * 16 + (lane & 15));
    const uint32_t aKl  = (uint32_t)((lane >> 4) << 4);
    const uint32_t bRow = (uint32_t)(((lane >> 4) << 3) + (lane & 7));
    const uint32_t bKl  = (uint32_t)(((lane >> 3) & 1) << 4);

    // Q fragment preload needs Q tile in smem (plain stores, no cp.async order dep)
    __syncthreads();
    uint32_t qh[4][4], ql[4][4];
    #pragma unroll
    for (int kk = 0; kk < 4; kk++) {
        uint32_t cofs = ((uint32_t)(kk << 5) + aKl) ^ swx;
        ldm4(qh[kk], sb + QHI + aRow * 128u + cofs);
        ldm4(ql[kk], sb + QLO + aRow * 128u + cofs);
    }

    float m_a = -1e30f, m_b = -1e30f, l_a = 0.f, l_b = 0.f;
    float oc[8][4];
    #pragma unroll
    for (int t = 0; t < 8; t++)
        #pragma unroll
        for (int r = 0; r < 4; r++) oc[t][r] = 0.f;

    #pragma unroll 1
    for (int kb = 0; kb < nkb; kb++) {
        CP_WAIT1();               // <=1 group outstanding -> tile kb landed
        __syncthreads();          // also: all reads of stage (kb+2)%3 done
        int s_cur = kb % 3;
        int s_pre = kb + 2; while (s_pre >= 3) s_pre -= 3;
        if (kb + 2 < nkb)
            load_kv_async(sb + STG0 + (uint32_t)s_pre * 32768u, kb + 2, b, bh, h, tid);
        CP_COMMIT();              // unconditional: keeps group count uniform
        const uint32_t sst = sb + STG0 + (uint32_t)s_cur * 32768u;

        float sc[8][4];
        #pragma unroll
        for (int t = 0; t < 8; t++)
            #pragma unroll
            for (int r = 0; r < 4; r++) sc[t][r] = 0.f;
        #pragma unroll
        for (int kk = 0; kk < 4; kk++) {
            uint32_t cofs = ((uint32_t)(kk << 5) + bKl) ^ swx;
            #pragma unroll
            for (int ng = 0; ng < 4; ng++) {
                uint32_t ro = (bRow + (uint32_t)(ng * 16)) * 128u;
                uint32_t kh[4], kl[4];
                ldm4(kh, sst + ro + cofs);
                ldm4(kl, sst + 8192u + ro + cofs);
                mma_bf16(sc[2*ng],   qh[kk], &kh[0]);
                mma_bf16(sc[2*ng+1], qh[kk], &kh[2]);
                mma_bf16(sc[2*ng],   qh[kk], &kl[0]);
                mma_bf16(sc[2*ng+1], qh[kk], &kl[2]);
                mma_bf16(sc[2*ng],   ql[kk], &kh[0]);
                mma_bf16(sc[2*ng+1], ql[kk], &kh[2]);
            }
        }

        const int rga = qb*128 + wid*16 + (lane >> 2);
        if (kb >= 2*qb) {
            #pragma unroll
            for (int t = 0; t < 8; t++) {
                int cg = kb*64 + t*8 + ((lane & 3) << 1);
                if (cg     > rga)     sc[t][0] = -1e30f;
                if (cg + 1 > rga)     sc[t][1] = -1e30f;
                if (cg     > rga + 8) sc[t][2] = -1e30f;
                if (cg + 1 > rga + 8) sc[t][3] = -1e30f;
            }
        }

        float mxa = -1e30f, mxb = -1e30f;
        #pragma unroll
        for (int t = 0; t < 8; t++) {
            mxa = fmaxf(mxa, fmaxf(sc[t][0], sc[t][1]));
            mxb = fmaxf(mxb, fmaxf(sc[t][2], sc[t][3]));
        }
        mxa = fmaxf(mxa, __shfl_xor_sync(0xffffffffu, mxa, 1));
        mxa = fmaxf(mxa, __shfl_xor_sync(0xffffffffu, mxa, 2));
        mxb = fmaxf(mxb, __shfl_xor_sync(0xffffffffu, mxb, 1));
        mxb = fmaxf(mxb, __shfl_xor_sync(0xffffffffu, mxb, 2));
        float mna = fmaxf(m_a, mxa), mnb = fmaxf(m_b, mxb);
        float alpa = __expf(m_a - mna), alpb = __expf(m_b - mnb);
        float psa = 0.f, psb = 0.f;
        #pragma unroll
        for (int t = 0; t < 8; t++) {
            sc[t][0] = __expf(sc[t][0] - mna); psa += sc[t][0];
            sc[t][1] = __expf(sc[t][1] - mna); psa += sc[t][1];
            sc[t][2] = __expf(sc[t][2] - mnb); psb += sc[t][2];
            sc[t][3] = __expf(sc[t][3] - mnb); psb += sc[t][3];
        }
        psa += __shfl_xor_sync(0xffffffffu, psa, 1);
        psa += __shfl_xor_sync(0xffffffffu, psa, 2);
        psb += __shfl_xor_sync(0xffffffffu, psb, 1);
        psb += __shfl_xor_sync(0xffffffffu, psb, 2);
        l_a = l_a * alpa + psa;  m_a = mna;
        l_b = l_b * alpb + psb;  m_b = mnb;
        #pragma unroll
        for (int t = 0; t < 8; t++) {
            oc[t][0] *= alpa; oc[t][1] *= alpa;
            oc[t][2] *= alpb; oc[t][3] *= alpb;
        }

        #pragma unroll
        for (int kk = 0; kk < 4; kk++) {
            uint32_t ph[4], pl[4];
            splitfast(sc[2*kk][0],   sc[2*kk][1],   ph[0], pl[0]);
            splitfast(sc[2*kk][2],   sc[2*kk][3],   ph[1], pl[1]);
            splitfast(sc[2*kk+1][0], sc[2*kk+1][1], ph[2], pl[2]);
            splitfast(sc[2*kk+1][2], sc[2*kk+1][3], ph[3], pl[3]);
            uint32_t cofs = ((uint32_t)(kk << 5) + bKl) ^ swx;
            #pragma unroll
            for (int ng = 0; ng < 4; ng++) {
                uint32_t ro = (bRow + (uint32_t)(ng * 16)) * 128u;
                uint32_t vh[4], vl[4];
                ldm4(vh, sst + 16384u + ro + cofs);
                ldm4(vl, sst + 24576u + ro + cofs);
                mma_bf16(oc[2*ng],   ph, &vh[0]);
                mma_bf16(oc[2*ng+1], ph, &vh[2]);
                mma_bf16(oc[2*ng],   ph, &vl[0]);
                mma_bf16(oc[2*ng+1], ph, &vl[2]);
                mma_bf16(oc[2*ng],   pl, &vh[0]);
                mma_bf16(oc[2*ng+1], pl, &vh[2]);
            }
        }
    }

    float inva = 1.f / l_a, invb = 1.f / l_b;
    int ra = qb*128 + wid*16 + (lane >> 2);
    size_t baseA = (size_t)(b*S_ + ra) * D_ + h*DH_;
    size_t baseB = baseA + (size_t)8 * D_;
    #pragma unroll
    for (int t = 0; t < 8; t++) {
        int d = t*8 + ((lane & 3) << 1);
        uint32_t hi, lo;
        splitfast(oc[t][0]*inva, oc[t][1]*inva, hi, lo);
        *(uint32_t*)&g_Chi[baseA + d] = hi;
        *(uint32_t*)&g_Clo[baseA + d] = lo;
        splitfast(oc[t][2]*invb, oc[t][3]*invb, hi, lo);
        *(uint32_t*)&g_Chi[baseB + d] = hi;
        *(uint32_t*)&g_Clo[baseB + d] = lo;
    }
}

// ===========================================================================
extern "C" void kernel_launch(void* const* d_in, const int* in_sizes, int n_in,
                              void* d_out, int out_size)
{
    const float* q  = (const float*)d_in[0];
    const float* k  = (const float*)d_in[1];
    const float* v  = (const float*)d_in[2];
    const float* Wq = (const float*)d_in[3];
    const float* bq = (const float*)d_in[4];
    const float* Wk = (const float*)d_in[5];
    const float* bk = (const float*)d_in[6];
    const float* Wv = (const float*)d_in[7];
    const float* bv = (const float*)d_in[8];
    const float* Wo = (const float*)d_in[9];
    const float* bo = (const float*)d_in[10];
    float* out = (float*)d_out;

    const int gsmem = 3 * 65536;  // 196608
    cudaFuncSetAttribute(gemm_qkv_kernel, cudaFuncAttributeMaxDynamicSharedMemorySize, gsmem);
    cudaFuncSetAttribute(gemm_o_kernel,   cudaFuncAttributeMaxDynamicSharedMemorySize, gsmem);
    const int asmem = 32768 + 3 * 32768;  // 131072
    cudaFuncSetAttribute(attn_mma_kernel, cudaFuncAttributeMaxDynamicSharedMemorySize, asmem);

    const int NXB = (int)(MD_/8)/256;   // 2048

    split_all_kernel<<<dim3(NXB, 1, 7), 256>>>(q, k, v, Wq, Wk, Wv, Wo);

    gemm_qkv_kernel<<<dim3(D_/128, MTOT/128, 3), 256, gsmem>>>(bq, bk, bv);

    vtrans_kernel<<<dim3(S_/64, B_*H_), 256>>>();

    attn_mma_kernel<<<dim3(S_/128, B_*H_), 256, asmem>>>();

    gemm_o_kernel<<<dim3(D_/128, MTOT/128), 256, gsmem>>>(bo, out);
}